// round 1
// baseline (speedup 1.0000x reference)
#include <cuda_runtime.h>
#include <cuda_bf16.h>
#include <math_constants.h>

#define THREADS 256
#define D 4096
#define VEC4_PER_ROW (D / 4)             // 1024 float4 per row
#define V4_PER_T (VEC4_PER_ROW / THREADS) // 4 float4 per thread -> 16 floats
#define ELEMS_PER_T (V4_PER_T * 4)
#define NWARPS (THREADS / 32)

__global__ __launch_bounds__(THREADS, 4)
void sparsemax_kernel(const float* __restrict__ in, float* __restrict__ out)
{
    const long long row = blockIdx.x;
    const float4* __restrict__ rin  = reinterpret_cast<const float4*>(in  + row * (long long)D);
    float4* __restrict__       rout = reinterpret_cast<float4*>      (out + row * (long long)D);

    const int t    = threadIdx.x;
    const int lane = t & 31;
    const int wid  = t >> 5;

    __shared__ float red_a[NWARPS];
    __shared__ float red_b[NWARPS];
    __shared__ float s_tau;
    __shared__ int   s_done;

    // ---- Load 16 elements per thread (coalesced float4 loads), keep in registers
    float z[ELEMS_PER_T];
#pragma unroll
    for (int i = 0; i < V4_PER_T; ++i) {
        float4 v = rin[t + i * THREADS];
        z[4 * i + 0] = v.x;
        z[4 * i + 1] = v.y;
        z[4 * i + 2] = v.z;
        z[4 * i + 3] = v.w;
    }

    // ---- Block max -> initial tau = z_max - 1  (bracket: f(z_max-1) >= 0)
    float m = -CUDART_INF_F;
#pragma unroll
    for (int i = 0; i < ELEMS_PER_T; ++i) m = fmaxf(m, z[i]);
#pragma unroll
    for (int off = 16; off >= 1; off >>= 1)
        m = fmaxf(m, __shfl_xor_sync(0xFFFFFFFFu, m, off));
    if (lane == 0) red_a[wid] = m;
    __syncthreads();
    if (t == 0) {
        float mm = red_a[0];
#pragma unroll
        for (int w = 1; w < NWARPS; ++w) mm = fmaxf(mm, red_a[w]);
        s_tau = mm - 1.0f;
    }
    __syncthreads();
    float tau = s_tau;

    // ---- Newton on f(tau) = sum(max(z - tau, 0)) - 1 ; f'(tau) = -count(z > tau)
    // Monotone from the left; block-uniform loop (break flag broadcast via smem).
    for (int it = 0; it < 48; ++it) {
        float s = 0.0f, k = 0.0f;
#pragma unroll
        for (int i = 0; i < ELEMS_PER_T; ++i) {
            float d = z[i] - tau;
            if (d > 0.0f) { s += d; k += 1.0f; }
        }
#pragma unroll
        for (int off = 16; off >= 1; off >>= 1) {
            s += __shfl_xor_sync(0xFFFFFFFFu, s, off);
            k += __shfl_xor_sync(0xFFFFFFFFu, k, off);
        }
        if (lane == 0) { red_a[wid] = s; red_b[wid] = k; }
        __syncthreads();
        if (t == 0) {
            float S = 0.0f, K = 0.0f;
#pragma unroll
            for (int w = 0; w < NWARPS; ++w) { S += red_a[w]; K += red_b[w]; }
            // K >= 1 while tau < z_max (guaranteed by bracket + convexity)
            float delta = (S - 1.0f) / K;
            s_tau  = tau + delta;
            s_done = (delta < 1e-7f);
        }
        __syncthreads();
        tau = s_tau;
        if (s_done) break;
    }

    // ---- Write output: max(z - tau, 0) (coalesced float4 stores)
#pragma unroll
    for (int i = 0; i < V4_PER_T; ++i) {
        float4 o;
        o.x = fmaxf(z[4 * i + 0] - tau, 0.0f);
        o.y = fmaxf(z[4 * i + 1] - tau, 0.0f);
        o.z = fmaxf(z[4 * i + 2] - tau, 0.0f);
        o.w = fmaxf(z[4 * i + 3] - tau, 0.0f);
        rout[t + i * THREADS] = o;
    }
}

extern "C" void kernel_launch(void* const* d_in, const int* in_sizes, int n_in,
                              void* d_out, int out_size)
{
    const float* in  = (const float*)d_in[0];
    float*       out = (float*)d_out;
    const int n_rows = in_sizes[0] / D;   // 16384
    sparsemax_kernel<<<n_rows, THREADS>>>(in, out);
}

// round 2
// speedup vs baseline: 1.0855x; 1.0855x over previous
#include <cuda_runtime.h>
#include <cuda_bf16.h>
#include <math_constants.h>

#define THREADS 512
#define D 4096
#define V4_PER_T (D / 4 / THREADS)        // 2 float4 per thread
#define ELEMS_PER_T (V4_PER_T * 4)        // 8 floats per thread
#define NWARPS (THREADS / 32)             // 16
#define CAP 2048                          // candidate buffer capacity

__global__ __launch_bounds__(THREADS, 4)
void sparsemax_kernel(const float* __restrict__ in, float* __restrict__ out)
{
    const long long row = blockIdx.x;
    const float4* __restrict__ rin  = reinterpret_cast<const float4*>(in  + row * (long long)D);
    float4* __restrict__       rout = reinterpret_cast<float4*>      (out + row * (long long)D);

    const int t    = threadIdx.x;
    const int lane = t & 31;
    const int wid  = t >> 5;

    __shared__ float red[NWARPS];
    __shared__ float red_b[NWARPS];
    __shared__ float cand[CAP];
    __shared__ int   s_cnt;
    __shared__ float s_tau;
    __shared__ int   s_done;

    if (t == 0) s_cnt = 0;

    // ---- Load 8 elements per thread (coalesced float4), keep in registers
    float z[ELEMS_PER_T];
#pragma unroll
    for (int i = 0; i < V4_PER_T; ++i) {
        float4 v = rin[t + i * THREADS];
        z[4 * i + 0] = v.x;
        z[4 * i + 1] = v.y;
        z[4 * i + 2] = v.z;
        z[4 * i + 3] = v.w;
    }

    // ---- Block max
    float m = z[0];
#pragma unroll
    for (int i = 1; i < ELEMS_PER_T; ++i) m = fmaxf(m, z[i]);
#pragma unroll
    for (int off = 16; off >= 1; off >>= 1)
        m = fmaxf(m, __shfl_xor_sync(0xFFFFFFFFu, m, off));
    if (lane == 0) red[wid] = m;
    __syncthreads();
    float zmax = red[0];
#pragma unroll
    for (int w = 1; w < NWARPS; ++w) zmax = fmaxf(zmax, red[w]);

    // ---- Compact candidates: only z > zmax - 1 can ever be in the support
    const float lo = zmax - 1.0f;
#pragma unroll
    for (int i = 0; i < ELEMS_PER_T; ++i) {
        if (z[i] > lo) {
            int pos = atomicAdd(&s_cnt, 1);
            if (pos < CAP) cand[pos] = z[i];
        }
    }
    __syncthreads();
    const int cnt = s_cnt;

    if (cnt <= CAP) {
        // ---- Warp 0 runs Newton over the tiny candidate set (no block barriers)
        if (wid == 0) {
            float tau = lo;
            for (int it = 0; it < 48; ++it) {
                float s = 0.0f, k = 0.0f;
                for (int j = lane; j < cnt; j += 32) {
                    float d = cand[j] - tau;
                    if (d > 0.0f) { s += d; k += 1.0f; }
                }
#pragma unroll
                for (int off = 16; off >= 1; off >>= 1) {
                    s += __shfl_xor_sync(0xFFFFFFFFu, s, off);
                    k += __shfl_xor_sync(0xFFFFFFFFu, k, off);
                }
                // all lanes hold identical s,k -> uniform control flow
                float delta = (s - 1.0f) / k;   // k >= 1 (zmax is a candidate)
                tau += delta;
                if (delta < 1e-7f) break;
            }
            if (lane == 0) s_tau = tau;
        }
        __syncthreads();
    } else {
        // ---- Fallback: block-wide Newton over all registers (correct for any data)
        if (t == 0) s_tau = lo;
        __syncthreads();
        float tau = s_tau;
        for (int it = 0; it < 48; ++it) {
            float s = 0.0f, k = 0.0f;
#pragma unroll
            for (int i = 0; i < ELEMS_PER_T; ++i) {
                float d = z[i] - tau;
                if (d > 0.0f) { s += d; k += 1.0f; }
            }
#pragma unroll
            for (int off = 16; off >= 1; off >>= 1) {
                s += __shfl_xor_sync(0xFFFFFFFFu, s, off);
                k += __shfl_xor_sync(0xFFFFFFFFu, k, off);
            }
            if (lane == 0) { red[wid] = s; red_b[wid] = k; }
            __syncthreads();
            if (t == 0) {
                float S = 0.0f, K = 0.0f;
#pragma unroll
                for (int w = 0; w < NWARPS; ++w) { S += red[w]; K += red_b[w]; }
                float delta = (S - 1.0f) / K;
                s_tau  = tau + delta;
                s_done = (delta < 1e-7f);
            }
            __syncthreads();
            tau = s_tau;
            if (s_done) break;
        }
    }

    const float tau = s_tau;

    // ---- Write output: max(z - tau, 0)
#pragma unroll
    for (int i = 0; i < V4_PER_T; ++i) {
        float4 o;
        o.x = fmaxf(z[4 * i + 0] - tau, 0.0f);
        o.y = fmaxf(z[4 * i + 1] - tau, 0.0f);
        o.z = fmaxf(z[4 * i + 2] - tau, 0.0f);
        o.w = fmaxf(z[4 * i + 3] - tau, 0.0f);
        rout[t + i * THREADS] = o;
    }
}

extern "C" void kernel_launch(void* const* d_in, const int* in_sizes, int n_in,
                              void* d_out, int out_size)
{
    const float* in  = (const float*)d_in[0];
    float*       out = (float*)d_out;
    const int n_rows = in_sizes[0] / D;   // 16384
    sparsemax_kernel<<<n_rows, THREADS>>>(in, out);
}

// round 3
// speedup vs baseline: 1.1620x; 1.0704x over previous
#include <cuda_runtime.h>
#include <cuda_bf16.h>
#include <math_constants.h>

#define THREADS 256
#define D 4096
#define V4T (D / 4 / THREADS)   // 4 float4 per thread
#define EPT (V4T * 4)           // 16 floats per thread
#define NW (THREADS / 32)       // 8 warps
#define SEG 32                  // per-warp candidate segment
#define MAXL NW                 // warp0 register slots (8 x 32 = 256 candidates)

__global__ __launch_bounds__(THREADS, 5)
void sparsemax_kernel(const float* __restrict__ in, float* __restrict__ out)
{
    const long long row = blockIdx.x;
    const float4* __restrict__ rin  = reinterpret_cast<const float4*>(in  + row * (long long)D);
    float4* __restrict__       rout = reinterpret_cast<float4*>      (out + row * (long long)D);

    const int t    = threadIdx.x;
    const int lane = t & 31;
    const int wid  = t >> 5;
    const unsigned FULL = 0xFFFFFFFFu;
    const unsigned lt_mask = (1u << lane) - 1u;

    __shared__ float red[NW];      // per-warp max
    __shared__ int   scnt[NW];     // per-warp candidate count
    __shared__ float redb[NW];     // fallback only
    __shared__ float cand[NW * SEG];
    __shared__ float s_tau;
    __shared__ int   s_ovf;
    __shared__ int   s_done;

    // ---- Load 16 elements/thread (4x LDG.128, coalesced, MLP=4)
    float z[EPT];
#pragma unroll
    for (int i = 0; i < V4T; ++i) {
        float4 v = rin[t + i * THREADS];
        z[4*i+0] = v.x; z[4*i+1] = v.y; z[4*i+2] = v.z; z[4*i+3] = v.w;
    }

    // ---- Intra-warp max (no cross-warp dependency before compaction)
    float m = z[0];
#pragma unroll
    for (int i = 1; i < EPT; ++i) m = fmaxf(m, z[i]);
#pragma unroll
    for (int off = 16; off >= 1; off >>= 1)
        m = fmaxf(m, __shfl_xor_sync(FULL, m, off));
    if (lane == 0) red[wid] = m;

    // ---- Per-warp compaction, threshold warpmax-1 (superset of true support; harmless)
    // Ballot/popc prefix into private segment: zero atomics.
    const float lo_w = m - 1.0f;
    unsigned wtot = 0;
#pragma unroll
    for (int i = 0; i < EPT; ++i) {
        bool p = z[i] > lo_w;
        unsigned msk = __ballot_sync(FULL, p);
        if (p) {
            int pos = (int)wtot + __popc(msk & lt_mask);
            if (pos < SEG) cand[(wid << 5) + pos] = z[i];
        }
        wtot += __popc(msk);
    }
    if (lane == 0) scnt[wid] = (int)wtot;
    __syncthreads();   // B1: segments + maxes + counts visible

    // ---- Warp 0: global max, gather candidates to registers, Newton (no barriers inside)
    if (wid == 0) {
        int   c0 = (lane < NW) ? scnt[lane] : 0;
        float m0 = (lane < NW) ? red[lane]  : -CUDART_INF_F;
        int   cmax = c0;
        float mm   = m0;
#pragma unroll
        for (int off = 4; off >= 1; off >>= 1) {
            cmax = max(cmax, __shfl_xor_sync(FULL, cmax, off));
            mm   = fmaxf(mm,  __shfl_xor_sync(FULL, mm,  off));
        }
        cmax = __shfl_sync(FULL, cmax, 0);
        mm   = __shfl_sync(FULL, mm,   0);

        int ovf = (cmax > SEG);
        float tau = mm - 1.0f;

        if (!ovf) {
            // gather segmented candidates into registers: v[j] = segment j, my lane
            float v[MAXL];
#pragma unroll
            for (int j = 0; j < MAXL; ++j) {
                int cj = __shfl_sync(FULL, c0, j);
                v[j] = (lane < cj) ? cand[(j << 5) + lane] : -CUDART_INF_F;
            }
            // Newton on f(tau) = sum(max(v - tau, 0)) - 1, monotone from tau0 = zmax-1
            for (int it = 0; it < 32; ++it) {
                float s = 0.0f, k = 0.0f;
#pragma unroll
                for (int j = 0; j < MAXL; ++j) {
                    float d = v[j] - tau;
                    if (d > 0.0f) { s += d; k += 1.0f; }
                }
#pragma unroll
                for (int off = 16; off >= 1; off >>= 1) {
                    s += __shfl_xor_sync(FULL, s, off);
                    k += __shfl_xor_sync(FULL, k, off);
                }
                float delta = (s - 1.0f) / k;   // k >= 1 (zmax is a candidate)
                tau += delta;
                if (delta < 1e-7f) break;       // uniform: s,k identical across lanes
            }
        }
        if (lane == 0) { s_tau = tau; s_ovf = ovf; }
    }
    __syncthreads();   // B2

    if (!s_ovf) {
        const float tau = s_tau;
#pragma unroll
        for (int i = 0; i < V4T; ++i) {
            float4 o;
            o.x = fmaxf(z[4*i+0] - tau, 0.0f);
            o.y = fmaxf(z[4*i+1] - tau, 0.0f);
            o.z = fmaxf(z[4*i+2] - tau, 0.0f);
            o.w = fmaxf(z[4*i+3] - tau, 0.0f);
            rout[t + i * THREADS] = o;
        }
        return;
    }

    // ---- Fallback (arbitrary adversarial data): block-wide Newton over registers
    {
        float zmax = red[0];
#pragma unroll
        for (int w = 1; w < NW; ++w) zmax = fmaxf(zmax, red[w]);
        if (t == 0) s_tau = zmax - 1.0f;
        __syncthreads();
        float tau = s_tau;
        for (int it = 0; it < 48; ++it) {
            float s = 0.0f, k = 0.0f;
#pragma unroll
            for (int i = 0; i < EPT; ++i) {
                float d = z[i] - tau;
                if (d > 0.0f) { s += d; k += 1.0f; }
            }
#pragma unroll
            for (int off = 16; off >= 1; off >>= 1) {
                s += __shfl_xor_sync(FULL, s, off);
                k += __shfl_xor_sync(FULL, k, off);
            }
            if (lane == 0) { red[wid] = s; redb[wid] = k; }
            __syncthreads();
            if (t == 0) {
                float S = 0.0f, K = 0.0f;
#pragma unroll
                for (int w = 0; w < NW; ++w) { S += red[w]; K += redb[w]; }
                float delta = (S - 1.0f) / K;
                s_tau  = tau + delta;
                s_done = (delta < 1e-7f);
            }
            __syncthreads();
            tau = s_tau;
            if (s_done) break;
        }
        const float tf = s_tau;
#pragma unroll
        for (int i = 0; i < V4T; ++i) {
            float4 o;
            o.x = fmaxf(z[4*i+0] - tf, 0.0f);
            o.y = fmaxf(z[4*i+1] - tf, 0.0f);
            o.z = fmaxf(z[4*i+2] - tf, 0.0f);
            o.w = fmaxf(z[4*i+3] - tf, 0.0f);
            rout[t + i * THREADS] = o;
        }
    }
}

extern "C" void kernel_launch(void* const* d_in, const int* in_sizes, int n_in,
                              void* d_out, int out_size)
{
    const float* in  = (const float*)d_in[0];
    float*       out = (float*)d_out;
    const int n_rows = in_sizes[0] / D;   // 16384
    sparsemax_kernel<<<n_rows, THREADS>>>(in, out);
}

// round 4
// speedup vs baseline: 1.4052x; 1.2093x over previous
#include <cuda_runtime.h>
#include <cuda_bf16.h>
#include <math_constants.h>

#define THREADS 256
#define D 4096
#define V4T (D / 4 / THREADS)   // 4 float4 per thread
#define EPT (V4T * 4)           // 16 floats per thread
#define NW (THREADS / 32)       // 8 warps
#define CANDCAP 64              // shared candidate buffer (guard)
#define SORTN 32                // fast path limit: one value per lane

__global__ __launch_bounds__(THREADS, 6)
void sparsemax_kernel(const float* __restrict__ in, float* __restrict__ out)
{
    const long long row = blockIdx.x;
    const float4* __restrict__ rin  = reinterpret_cast<const float4*>(in  + row * (long long)D);
    float4* __restrict__       rout = reinterpret_cast<float4*>      (out + row * (long long)D);

    const int t    = threadIdx.x;
    const int lane = t & 31;
    const int wid  = t >> 5;
    const unsigned FULL = 0xFFFFFFFFu;

    __shared__ float red[NW];
    __shared__ float redb[NW];
    __shared__ float cand[CANDCAP];
    __shared__ int   s_cnt;
    __shared__ float s_tau;
    __shared__ int   s_done;

    if (t == 0) s_cnt = 0;

    // ---- Load 16 elements/thread, keep quad maxes for the skip-filter
    float z[EPT];
    float qm[V4T];
#pragma unroll
    for (int i = 0; i < V4T; ++i) {
        float4 v = rin[t + i * THREADS];
        z[4*i+0] = v.x; z[4*i+1] = v.y; z[4*i+2] = v.z; z[4*i+3] = v.w;
        qm[i] = fmaxf(fmaxf(v.x, v.y), fmaxf(v.z, v.w));
    }

    // ---- Warp max, then block max via smem
    float m = fmaxf(fmaxf(qm[0], qm[1]), fmaxf(qm[2], qm[3]));
#pragma unroll
    for (int off = 16; off >= 1; off >>= 1)
        m = fmaxf(m, __shfl_xor_sync(FULL, m, off));
    if (lane == 0) red[wid] = m;
    __syncthreads();                       // B0: maxes + s_cnt=0 visible

    float zmax = red[0];
#pragma unroll
    for (int w = 1; w < NW; ++w) zmax = fmaxf(zmax, red[w]);
    const float lo = zmax - 1.0f;          // tau in [lo, zmax): only z > lo matter

    // ---- Compaction with quad-skip: only ~35% of quad rounds have any candidate
    // warp-wide; uniform-address atomicAdd is REDUX-aggregated by ptxas.
#pragma unroll
    for (int q = 0; q < V4T; ++q) {
        if (__any_sync(FULL, qm[q] > lo)) {
#pragma unroll
            for (int e = 0; e < 4; ++e) {
                float val = z[4*q + e];
                if (val > lo) {
                    int pos = atomicAdd(&s_cnt, 1);
                    if (pos < CANDCAP) cand[pos] = val;
                }
            }
        }
    }
    __syncthreads();                       // B1: candidates visible
    const int cnt = s_cnt;

    float tau;
    if (cnt <= SORTN) {
        // ---- Exact solve, redundantly in EVERY warp (no serial tail, no 3rd barrier)
        float v = (lane < cnt) ? cand[lane] : -CUDART_INF_F;

        // 32-lane bitonic sort, descending (canonical network, comparator inverted)
#pragma unroll
        for (int k = 2; k <= 32; k <<= 1) {
#pragma unroll
            for (int j = k >> 1; j > 0; j >>= 1) {
                float w = __shfl_xor_sync(FULL, v, j);
                bool lower   = ((lane & j) == 0);
                bool descBlk = ((lane & k) == 0);
                v = (lower == descBlk) ? fmaxf(v, w) : fminf(v, w);
            }
        }

        // inclusive prefix sum of sorted-descending values
        float csum = v;
#pragma unroll
        for (int off = 1; off < 32; off <<= 1) {
            float u = __shfl_up_sync(FULL, csum, off);
            if (lane >= off) csum += u;
        }

        // support size: largest j with 1 + (j+1)*v_j > csum_j  (lane 0 always true)
        float r = (float)(lane + 1);
        bool cond = (lane < cnt) && (1.0f + r * v > csum);
        unsigned msk = __ballot_sync(FULL, cond);
        int kidx = 31 - __clz(msk);
        float csk = __shfl_sync(FULL, csum, kidx);
        tau = (csk - 1.0f) / (float)(kidx + 1);
        // identical bitwise across warps -> no sync needed
    } else {
        // ---- Fallback for arbitrary data: block-wide Newton over registers
        if (t == 0) s_tau = lo;
        __syncthreads();
        float tloc = s_tau;
        for (int it = 0; it < 48; ++it) {
            float s = 0.0f, k = 0.0f;
#pragma unroll
            for (int i = 0; i < EPT; ++i) {
                float d = z[i] - tloc;
                if (d > 0.0f) { s += d; k += 1.0f; }
            }
#pragma unroll
            for (int off = 16; off >= 1; off >>= 1) {
                s += __shfl_xor_sync(FULL, s, off);
                k += __shfl_xor_sync(FULL, k, off);
            }
            if (lane == 0) { red[wid] = s; redb[wid] = k; }
            __syncthreads();
            if (t == 0) {
                float S = 0.0f, K = 0.0f;
#pragma unroll
                for (int w = 0; w < NW; ++w) { S += red[w]; K += redb[w]; }
                float delta = (S - 1.0f) / K;
                s_tau  = tloc + delta;
                s_done = (delta < 1e-7f);
            }
            __syncthreads();
            tloc = s_tau;
            if (s_done) break;
        }
        tau = s_tau;
    }

    // ---- Epilogue: out = max(z - tau, 0), coalesced float4 stores
#pragma unroll
    for (int i = 0; i < V4T; ++i) {
        float4 o;
        o.x = fmaxf(z[4*i+0] - tau, 0.0f);
        o.y = fmaxf(z[4*i+1] - tau, 0.0f);
        o.z = fmaxf(z[4*i+2] - tau, 0.0f);
        o.w = fmaxf(z[4*i+3] - tau, 0.0f);
        rout[t + i * THREADS] = o;
    }
}

extern "C" void kernel_launch(void* const* d_in, const int* in_sizes, int n_in,
                              void* d_out, int out_size)
{
    const float* in  = (const float*)d_in[0];
    float*       out = (float*)d_out;
    const int n_rows = in_sizes[0] / D;   // 16384
    sparsemax_kernel<<<n_rows, THREADS>>>(in, out);
}